// round 10
// baseline (speedup 1.0000x reference)
#include <cuda_runtime.h>
#include <cstdint>

#define B_DIM 8
#define C_DIM 4
#define T_DIM 262144
#define U64_PER_CH (T_DIM / 2)     // 131072 u64 per channel
#define CHUNKS_PER_CH (T_DIM / 8)  // 32768 32-byte chunks per channel

#define NTHREADS 128
#define BLK_PER_BATCH 74
#define NBLOCKS (BLK_PER_BATCH * B_DIM)   // 592 = 4 * 148 -> perfect SM balance
#define STRIDE (BLK_PER_BATCH * NTHREADS) // 9472 threads per batch

typedef unsigned long long u64;

// Scratch (zero-init at load; last block resets -> clean state each replay)
__device__ float g_partial[B_DIM][16];
__device__ unsigned int g_ticket;

__device__ __forceinline__ u64 ffma2(u64 a, u64 b, u64 c) {
    u64 d;
    asm("fma.rn.f32x2 %0, %1, %2, %3;" : "=l"(d) : "l"(a), "l"(b), "l"(c));
    return d;
}

// 256-bit global load (sm_100+): 4 x u64 = 32 bytes, 32B-aligned.
__device__ __forceinline__ void ldg256(const u64* p, u64& a, u64& b, u64& c, u64& d) {
    asm("ld.global.v4.b64 {%0, %1, %2, %3}, [%4];"
        : "=l"(a), "=l"(b), "=l"(c), "=l"(d) : "l"(p));
}

__global__ void __launch_bounds__(NTHREADS) pit_bal_kernel(
    const float* __restrict__ x, const float* __restrict__ y,
    float* __restrict__ out) {
    const int tid = threadIdx.x;
    const int lane = tid & 31;
    const int b = blockIdx.y;

    const u64* __restrict__ xb = (const u64*)(x + (long long)b * C_DIM * T_DIM);
    const u64* __restrict__ yb = (const u64*)(y + (long long)b * C_DIM * T_DIM);

    const u64 NEG1 = 0xBF800000BF800000ULL;  // packed (-1.0f, -1.0f)

    u64 acc[16];
#pragma unroll
    for (int k = 0; k < 16; k++) acc[k] = 0ULL;

    // Grid-stride over 32-byte column chunks (3 or 4 iterations per thread;
    // the mix is identical in every block -> every SM carries equal work).
    for (int col = blockIdx.x * NTHREADS + tid; col < CHUNKS_PER_CH; col += STRIDE) {
        const long long off = (long long)col * 4;  // u64 index
        u64 xv[C_DIM][4], yv[C_DIM][4];
#pragma unroll
        for (int c = 0; c < C_DIM; c++) {
            ldg256(xb + (long long)c * U64_PER_CH + off,
                   xv[c][0], xv[c][1], xv[c][2], xv[c][3]);
            ldg256(yb + (long long)c * U64_PER_CH + off,
                   yv[c][0], yv[c][1], yv[c][2], yv[c][3]);
        }
#pragma unroll
        for (int i = 0; i < C_DIM; i++) {
#pragma unroll
            for (int j = 0; j < C_DIM; j++) {
                u64 a = acc[i * 4 + j];
#pragma unroll
                for (int q = 0; q < 4; q++) {
                    u64 d = ffma2(yv[i][q], NEG1, xv[j][q]);  // x - y (exact)
                    a = ffma2(d, d, a);
                }
                acc[i * 4 + j] = a;
            }
        }
    }

    // Unpack f32x2 accumulators -> 16 scalars per lane
    float v[16];
#pragma unroll
    for (int k = 0; k < 16; k++) {
        float lo = __uint_as_float((unsigned)(acc[k] & 0xFFFFFFFFULL));
        float hi = __uint_as_float((unsigned)(acc[k] >> 32));
        v[k] = lo + hi;
    }

    // Multi-value butterfly warp reduction (16 shuffles).
    // After the steps, lane l (l<16) owns acc index bitrev4(l).
#pragma unroll
    for (int j = 0; j < 8; j++) {
        float send = (lane & 1) ? v[j] : v[j + 8];
        float recv = __shfl_xor_sync(0xffffffff, send, 1);
        v[j] = ((lane & 1) ? v[j + 8] : v[j]) + recv;
    }
#pragma unroll
    for (int j = 0; j < 4; j++) {
        float send = (lane & 2) ? v[j] : v[j + 4];
        float recv = __shfl_xor_sync(0xffffffff, send, 2);
        v[j] = ((lane & 2) ? v[j + 4] : v[j]) + recv;
    }
#pragma unroll
    for (int j = 0; j < 2; j++) {
        float send = (lane & 4) ? v[j] : v[j + 2];
        float recv = __shfl_xor_sync(0xffffffff, send, 4);
        v[j] = ((lane & 4) ? v[j + 2] : v[j]) + recv;
    }
    {
        float send = (lane & 8) ? v[0] : v[1];
        float recv = __shfl_xor_sync(0xffffffff, send, 8);
        v[0] = ((lane & 8) ? v[1] : v[0]) + recv;
    }
    v[0] += __shfl_xor_sync(0xffffffff, v[0], 16);
    const int idx = ((lane & 1) << 3) | ((lane & 2) << 1) |
                    ((lane & 4) >> 1) | ((lane & 8) >> 3);

    __shared__ float s_acc[16];
    __shared__ float s_d[B_DIM * 16];
    __shared__ bool s_is_last;

    if (tid < 16) s_acc[tid] = 0.0f;
    __syncthreads();
    if (lane < 16) atomicAdd(&s_acc[idx], v[0]);
    __syncthreads();
    if (tid < 16) atomicAdd(&g_partial[b][tid], s_acc[tid]);

    // ---- last-block-done finalize ----
    __threadfence();
    if (tid == 0) {
        unsigned int t = atomicAdd(&g_ticket, 1u);
        s_is_last = (t == NBLOCKS - 1);
    }
    __syncthreads();
    if (!s_is_last) return;

    if (tid < B_DIM * 16)
        s_d[tid] = __ldcg(&((const float*)g_partial)[tid]);
    __syncthreads();

    if (tid == 0) {
        const float inv_t = 1.0f / (float)T_DIM;
        float total = 0.0f;
        for (int bb = 0; bb < B_DIM; bb++) {
            const float* d = &s_d[bb * 16];
            float best = 3.4e38f;
            for (int p0 = 0; p0 < 4; p0++)
                for (int p1 = 0; p1 < 4; p1++) {
                    if (p1 == p0) continue;
                    for (int p2 = 0; p2 < 4; p2++) {
                        if (p2 == p0 || p2 == p1) continue;
                        int p3 = 6 - p0 - p1 - p2;
                        float c = d[0 * 4 + p0] + d[1 * 4 + p1] +
                                  d[2 * 4 + p2] + d[3 * 4 + p3];
                        best = fminf(best, c);
                    }
                }
            total += best * inv_t;
        }
        out[0] = total;
        g_ticket = 0;
    }
    if (tid < B_DIM * 16)
        ((float*)g_partial)[tid] = 0.0f;
}

extern "C" void kernel_launch(void* const* d_in, const int* in_sizes, int n_in,
                              void* d_out, int out_size) {
    const float* x = (const float*)d_in[0];
    const float* y = (const float*)d_in[1];
    float* out = (float*)d_out;

    dim3 grid(BLK_PER_BATCH, B_DIM);
    pit_bal_kernel<<<grid, NTHREADS>>>(x, y, out);
}

// round 12
// speedup vs baseline: 1.1830x; 1.1830x over previous
#include <cuda_runtime.h>
#include <cstdint>

#define B_DIM 8
#define C_DIM 4
#define T_DIM 262144
#define T4 (T_DIM / 4)                    // ulonglong2 (16B) chunks per channel

#define NTHREADS 128
#define BLK_PER_BATCH 64
#define NBLOCKS (BLK_PER_BATCH * B_DIM)   // 512
#define ITERS 8                           // 64 * 128 * 8 = 65536 = T4

#define NVALS 24                          // 16 cross + 4 sx + 4 sy per batch

typedef unsigned long long u64;

// Scratch (zero-init at load; last block resets -> clean state each replay)
__device__ float g_partial[B_DIM][NVALS];
__device__ unsigned int g_ticket;

__device__ __forceinline__ u64 ffma2(u64 a, u64 b, u64 c) {
    u64 d;
    asm("fma.rn.f32x2 %0, %1, %2, %3;" : "=l"(d) : "l"(a), "l"(b), "l"(c));
    return d;
}

__global__ void __launch_bounds__(NTHREADS) pit_polar_kernel(
    const float* __restrict__ x, const float* __restrict__ y,
    float* __restrict__ out) {
    const int tid = threadIdx.x;
    const int lane = tid & 31;
    const int b = blockIdx.y;

    const ulonglong2* __restrict__ x2 =
        (const ulonglong2*)(x + (long long)b * C_DIM * T_DIM);
    const ulonglong2* __restrict__ y2 =
        (const ulonglong2*)(y + (long long)b * C_DIM * T_DIM);

    u64 cross[16], sx[4], sy[4];
#pragma unroll
    for (int k = 0; k < 16; k++) cross[k] = 0ULL;
#pragma unroll
    for (int k = 0; k < 4; k++) { sx[k] = 0ULL; sy[k] = 0ULL; }

    const int base = blockIdx.x * (NTHREADS * ITERS) + tid;
#pragma unroll 2
    for (int it = 0; it < ITERS; it++) {
        const int col = base + it * NTHREADS;
        ulonglong2 xv[C_DIM], yv[C_DIM];
#pragma unroll
        for (int c = 0; c < C_DIM; c++) {
            xv[c] = x2[c * T4 + col];
            yv[c] = y2[c * T4 + col];
        }
#pragma unroll
        for (int c = 0; c < C_DIM; c++) {
            sx[c] = ffma2(xv[c].x, xv[c].x, sx[c]);
            sx[c] = ffma2(xv[c].y, xv[c].y, sx[c]);
            sy[c] = ffma2(yv[c].x, yv[c].x, sy[c]);
            sy[c] = ffma2(yv[c].y, yv[c].y, sy[c]);
        }
#pragma unroll
        for (int i = 0; i < C_DIM; i++) {
#pragma unroll
            for (int j = 0; j < C_DIM; j++) {
                u64 a = cross[i * 4 + j];
                a = ffma2(xv[j].x, yv[i].x, a);
                a = ffma2(xv[j].y, yv[i].y, a);
                cross[i * 4 + j] = a;
            }
        }
    }

    // Unpack f32x2 accumulators -> scalars
    float v[16], sq[8];
#pragma unroll
    for (int k = 0; k < 16; k++) {
        float lo = __uint_as_float((unsigned)(cross[k] & 0xFFFFFFFFULL));
        float hi = __uint_as_float((unsigned)(cross[k] >> 32));
        v[k] = lo + hi;
    }
#pragma unroll
    for (int k = 0; k < 4; k++) {
        sq[k] = __uint_as_float((unsigned)(sx[k] & 0xFFFFFFFFULL)) +
                __uint_as_float((unsigned)(sx[k] >> 32));
        sq[4 + k] = __uint_as_float((unsigned)(sy[k] & 0xFFFFFFFFULL)) +
                    __uint_as_float((unsigned)(sy[k] >> 32));
    }

    // Butterfly warp reduction on the 16 cross sums (16 shuffles);
    // lane l (l<16) ends owning cross index bitrev4(l).
#pragma unroll
    for (int j = 0; j < 8; j++) {
        float send = (lane & 1) ? v[j] : v[j + 8];
        float recv = __shfl_xor_sync(0xffffffff, send, 1);
        v[j] = ((lane & 1) ? v[j + 8] : v[j]) + recv;
    }
#pragma unroll
    for (int j = 0; j < 4; j++) {
        float send = (lane & 2) ? v[j] : v[j + 4];
        float recv = __shfl_xor_sync(0xffffffff, send, 2);
        v[j] = ((lane & 2) ? v[j + 4] : v[j]) + recv;
    }
#pragma unroll
    for (int j = 0; j < 2; j++) {
        float send = (lane & 4) ? v[j] : v[j + 2];
        float recv = __shfl_xor_sync(0xffffffff, send, 4);
        v[j] = ((lane & 4) ? v[j + 2] : v[j]) + recv;
    }
    {
        float send = (lane & 8) ? v[0] : v[1];
        float recv = __shfl_xor_sync(0xffffffff, send, 8);
        v[0] = ((lane & 8) ? v[1] : v[0]) + recv;
    }
    v[0] += __shfl_xor_sync(0xffffffff, v[0], 16);
    const int idx = ((lane & 1) << 3) | ((lane & 2) << 1) |
                    ((lane & 4) >> 1) | ((lane & 8) >> 3);

    // Naive shuffle reduction for the 8 square sums
#pragma unroll
    for (int k = 0; k < 8; k++) {
#pragma unroll
        for (int off = 16; off > 0; off >>= 1)
            sq[k] += __shfl_down_sync(0xffffffff, sq[k], off);
    }

    __shared__ float s_acc[NVALS];
    __shared__ float s_d[B_DIM * NVALS];
    __shared__ bool s_is_last;

    if (tid < NVALS) s_acc[tid] = 0.0f;
    __syncthreads();
    if (lane < 16) atomicAdd(&s_acc[idx], v[0]);
    if (lane == 0) {
#pragma unroll
        for (int k = 0; k < 8; k++) atomicAdd(&s_acc[16 + k], sq[k]);
    }
    __syncthreads();
    if (tid < NVALS) atomicAdd(&g_partial[b][tid], s_acc[tid]);

    // ---- last-block-done finalize ----
    __threadfence();
    if (tid == 0) {
        unsigned int t = atomicAdd(&g_ticket, 1u);
        s_is_last = (t == NBLOCKS - 1);
    }
    __syncthreads();
    if (!s_is_last) return;

    // NOTE: B_DIM*NVALS = 192 > NTHREADS = 128 -> must stride!
    for (int k = tid; k < B_DIM * NVALS; k += NTHREADS)
        s_d[k] = __ldcg(&((const float*)g_partial)[k]);
    __syncthreads();

    if (tid == 0) {
        const float inv_t = 1.0f / (float)T_DIM;
        float total = 0.0f;
        for (int bb = 0; bb < B_DIM; bb++) {
            const float* p = &s_d[bb * NVALS];
            // dist_ij * T = Sx_j + Sy_i - 2*Cross_ij
            float d[16];
#pragma unroll
            for (int i = 0; i < 4; i++)
#pragma unroll
                for (int j = 0; j < 4; j++)
                    d[i * 4 + j] = p[16 + j] + p[20 + i] - 2.0f * p[i * 4 + j];
            float best = 3.4e38f;
            for (int p0 = 0; p0 < 4; p0++)
                for (int p1 = 0; p1 < 4; p1++) {
                    if (p1 == p0) continue;
                    for (int p2 = 0; p2 < 4; p2++) {
                        if (p2 == p0 || p2 == p1) continue;
                        int p3 = 6 - p0 - p1 - p2;
                        float c = d[0 * 4 + p0] + d[1 * 4 + p1] +
                                  d[2 * 4 + p2] + d[3 * 4 + p3];
                        best = fminf(best, c);
                    }
                }
            total += best * inv_t;
        }
        out[0] = total;
        g_ticket = 0;
    }
    // Strided reset (192 words, 128 threads)
    for (int k = tid; k < B_DIM * NVALS; k += NTHREADS)
        ((float*)g_partial)[k] = 0.0f;
}

extern "C" void kernel_launch(void* const* d_in, const int* in_sizes, int n_in,
                              void* d_out, int out_size) {
    const float* x = (const float*)d_in[0];
    const float* y = (const float*)d_in[1];
    float* out = (float*)d_out;

    dim3 grid(BLK_PER_BATCH, B_DIM);
    pit_polar_kernel<<<grid, NTHREADS>>>(x, y, out);
}